// round 16
// baseline (speedup 1.0000x reference)
#include <cuda_runtime.h>
#include <cuda_fp16.h>
#include <cstdint>

#define NB 8
#define NT 1024
#define NC 512
#define NH 4
#define BT (NB*NT)          // 8192
#define NF 2048             // NH*NC

// ---------------- scratch (device globals) ----------------
__device__ __half g_h[BT * NC];                     // [bt][c]
__device__ __half g_qkT[(long long)4096 * BT];      // rows 0..2047 Q(h*512+c), 2048..4095 K ; [row][bt]
__device__ __half g_v2[(long long)BT * NF];         // [bt][h*512+d]
__device__ __half g_attnh[32 * NC * NC];            // [z][c][d]: E = exp(logit-2), fp16
__device__ float  g_Z[32 * NC];                     // row sums of E (atomic-accumulated)
__device__ __half g_av2[(long long)BT * NF];        // [bt][h*512+c]
__device__ __half g_wqkT[6144 * NC];                // [row][c] row: sec*2048 + h*512 + c (sec 2 = V)
__device__ __half g_woutT[NC * NF];                 // [c][f]
__device__ int    g_cnt[64];                        // AV completion counters [b*8 + t-tile]
__device__ int    g_cnt2a[256];                     // qkT tile counters [ft*8 + b], target 8

__device__ __forceinline__ uint32_t smem_u32(const void* p) {
    uint32_t a;
    asm("{ .reg .u64 t; cvta.to.shared.u64 t, %1; cvt.u32.u64 %0, t; }" : "=r"(a) : "l"(p));
    return a;
}
#define SWZ(o) ((o) ^ (((o) >> 3) & 0x70))

#define CPASYNC16(dst, src) \
    asm volatile("cp.async.cg.shared.global [%0], [%1], 16;" :: "r"(dst), "l"(src))
#define CP_COMMIT() asm volatile("cp.async.commit_group;" ::: "memory")
#define CP_WAIT1()  asm volatile("cp.async.wait_group 1;" ::: "memory")

#define LDSM4(r0, r1, r2, r3, addr) \
    asm volatile("ldmatrix.sync.aligned.m8n8.x4.shared.b16 {%0,%1,%2,%3}, [%4];" \
        : "=r"(r0), "=r"(r1), "=r"(r2), "=r"(r3) : "r"(addr))

#define HMMA16(d, a0, a1, a2, a3, b0, b1) \
    asm volatile("mma.sync.aligned.m16n8k16.row.col.f32.f16.f16.f32 " \
        "{%0,%1,%2,%3}, {%4,%5,%6,%7}, {%8,%9}, {%0,%1,%2,%3};" \
        : "+f"((d)[0]), "+f"((d)[1]), "+f"((d)[2]), "+f"((d)[3]) \
        : "r"(a0), "r"(a1), "r"(a2), "r"(a3), "r"(b0), "r"(b1))

// ---------------- merged prep: groupnorm + transposes + counter/Z zero ----------
__global__ void gn_tr(const float* __restrict__ x,
                      const float* __restrict__ scale,
                      const float* __restrict__ bias,
                      const float* __restrict__ wqkv,
                      const float* __restrict__ wout) {
    int blk = blockIdx.x;
    int tid = threadIdx.x;
    if (blk < 256) {
        int b = blk >> 5, g = blk & 31;
        if (blk < 64) g_Z[blk * 256 + tid] = 0.f;
        if (blk == 64 && tid < 64) g_cnt[tid] = 0;
        if (blk == 65) g_cnt2a[tid] = 0;
        const float* base = x + (size_t)b * (NT * NC) + g * 16;
        __half* hbase = g_h + (size_t)b * (NT * NC) + g * 16;
        int col = tid & 15;
        float sc = scale[g * 16 + col];
        float bi = bias[g * 16 + col];
        float s = 0.f, ss = 0.f;
        for (int idx = tid; idx < NT * 16; idx += 256) {
            float v = base[(idx >> 4) * NC + (idx & 15)];
            s += v; ss += v * v;
        }
        for (int o = 16; o; o >>= 1) {
            s  += __shfl_xor_sync(0xffffffffu, s,  o);
            ss += __shfl_xor_sync(0xffffffffu, ss, o);
        }
        __shared__ float sa[8], sb[8];
        __shared__ float s_mean, s_rstd;
        int wid = tid >> 5;
        if ((tid & 31) == 0) { sa[wid] = s; sb[wid] = ss; }
        __syncthreads();
        if (tid == 0) {
            float S = 0.f, SS = 0.f;
            #pragma unroll
            for (int i = 0; i < 8; i++) { S += sa[i]; SS += sb[i]; }
            float inv = 1.0f / (NT * 16);
            float mean = S * inv;
            float var  = SS * inv - mean * mean;
            s_mean = mean;
            s_rstd = rsqrtf(var + 1e-5f);
        }
        __syncthreads();
        float mean = s_mean, rstd = s_rstd;
        for (int idx = tid; idx < NT * 16; idx += 256) {
            int off = (idx >> 4) * NC + (idx & 15);
            hbase[off] = __float2half((base[off] - mean) * rstd * sc + bi);
        }
        return;
    }
    __shared__ float t[32][33];
    int tx = tid & 31, ty = tid >> 5;
    if (blk < 448) {
        int q = blk - 256;
        int sec = q >> 6;
        int within = q & 63;
        int h = within >> 4, ct = within & 15;
        int c0 = ct * 32;
        int fbase = h * 1536 + sec;
        int r0 = sec * 2048 + h * 512 + c0;
        for (int k0 = 0; k0 < 512; k0 += 32) {
            #pragma unroll
            for (int j = 0; j < 4; j++) {
                int k = ty + j * 8;
                t[k][tx] = wqkv[(long long)(k0 + k) * 6144 + fbase + 3 * (c0 + tx)];
            }
            __syncthreads();
            #pragma unroll
            for (int j = 0; j < 4; j++) {
                int cc = ty + j * 8;
                g_wqkT[(long long)(r0 + cc) * 512 + k0 + tx] = __float2half(t[tx][cc]);
            }
            __syncthreads();
        }
    } else {
        int q = blk - 448;
        int f0 = (q & 63) * 32, c0 = (q >> 6) * 32;
        #pragma unroll
        for (int j = 0; j < 4; j++)
            t[ty + j * 8][tx] = wout[(long long)(f0 + ty + j * 8) * 512 + c0 + tx];
        __syncthreads();
        #pragma unroll
        for (int j = 0; j < 4; j++)
            g_woutT[(long long)(c0 + ty + j * 8) * 2048 + f0 + tx] = __float2half(t[tx][ty + j * 8]);
    }
}

// ---------------- fp16 mma.sync GEMM body: CTA 128x128, warp 64x32, BK=64 ------
#define STAGEB 32768
#define NSTAGE 3
#define GSMEM (NSTAGE * STAGEB)

__device__ __forceinline__ int qkv_map_m(int r) {
    int sec = r >> 11, rem = r & 2047;
    return (rem >> 9) * 1536 + 3 * (rem & 511) + sec;
}
__device__ __forceinline__ int qkv_map_v(int n) {
    return (n >> 9) * 1536 + 3 * (n & 511) + 2;
}

__device__ __forceinline__ void gemm_body(
        char* smem,
        const __half* __restrict__ A, const __half* __restrict__ B, void* __restrict__ Cv,
        int K, int Asm, int Bsn, int Csm, long long cbase, int m0, int n0,
        float alpha,
        const float* __restrict__ bias_m, const float* __restrict__ bias_n,
        const float* __restrict__ resid, int c16, int bmode,
        const float* __restrict__ rowscale, long long rsbase,
        float* __restrict__ zsum, long long zbase, int emode) {
    uint32_t sbase = smem_u32(smem);
    int tid = threadIdx.x, lane = tid & 31, wid = tid >> 5;
    int g = lane >> 2, qid = lane & 3;
    int wm = (wid & 1) * 64, wn = (wid >> 1) * 32;

    A += (long long)m0 * Asm;
    B += (long long)n0 * Bsn;

    int row0 = tid >> 3, q0 = tid & 7;
    const __half* srcA = A + (long long)row0 * Asm + q0 * 8;
    const __half* srcB = B + (long long)row0 * Bsn + q0 * 8;
    uint32_t dstA = sbase + SWZ((uint32_t)(row0 * 128 + q0 * 16));

    float acc[4][4][4];
    #pragma unroll
    for (int i = 0; i < 4; i++)
        #pragma unroll
        for (int j = 0; j < 4; j++)
            #pragma unroll
            for (int qq = 0; qq < 4; qq++) acc[i][j][qq] = 0.f;

    int KB = K >> 6;

    #pragma unroll
    for (int s = 0; s < 2; s++) {
        uint32_t so = s * STAGEB;
        #pragma unroll
        for (int t = 0; t < 4; t++) {
            CPASYNC16(dstA + so + t * 4096,         srcA + s * 64 + (long long)(32 * t) * Asm);
            CPASYNC16(dstA + so + 16384 + t * 4096, srcB + s * 64 + (long long)(32 * t) * Bsn);
        }
        CP_COMMIT();
    }

    uint32_t baseA = (uint32_t)((wm + (lane & 15)) * 128 + (lane >> 4) * 16);
    uint32_t baseB = (uint32_t)((wn + (lane & 7) + ((lane >> 4) & 1) * 8) * 128 + ((lane >> 3) & 1) * 16);

    int st = 0;
    for (int kb = 0; kb < KB; kb++) {
        CP_WAIT1();
        __syncthreads();
        if (kb + 2 < KB) {
            int s2 = st + 2; if (s2 >= NSTAGE) s2 -= NSTAGE;
            uint32_t so = (uint32_t)s2 * STAGEB;
            #pragma unroll
            for (int t = 0; t < 4; t++) {
                CPASYNC16(dstA + so + t * 4096,         srcA + (kb + 2) * 64 + (long long)(32 * t) * Asm);
                CPASYNC16(dstA + so + 16384 + t * 4096, srcB + (kb + 2) * 64 + (long long)(32 * t) * Bsn);
            }
        }
        CP_COMMIT();

        uint32_t sA = sbase + st * STAGEB;
        uint32_t sB = sA + 16384;

        #pragma unroll
        for (int ks = 0; ks < 4; ks++) {
            uint32_t a[4][4], bf[2][4];
            #pragma unroll
            for (int mt = 0; mt < 4; mt++)
                LDSM4(a[mt][0], a[mt][1], a[mt][2], a[mt][3],
                      sA + SWZ(baseA + mt * 2048 + ks * 32));
            #pragma unroll
            for (int ntp = 0; ntp < 2; ntp++)
                LDSM4(bf[ntp][0], bf[ntp][1], bf[ntp][2], bf[ntp][3],
                      sB + SWZ(baseB + ntp * 2048 + ks * 32));
            #pragma unroll
            for (int mt = 0; mt < 4; mt++)
                #pragma unroll
                for (int nt = 0; nt < 4; nt++) {
                    uint32_t b0 = bf[nt >> 1][(nt & 1) * 2];
                    uint32_t b1 = bf[nt >> 1][(nt & 1) * 2 + 1];
                    HMMA16(acc[mt][nt], a[mt][0], a[mt][1], a[mt][2], a[mt][3], b0, b1);
                }
        }
        st++; if (st == NSTAGE) st = 0;
    }

    // ---------------- epilogue ----------------
    #pragma unroll
    for (int mt = 0; mt < 4; mt++) {
        int r = m0 + wm + 16 * mt + g;
        float bm0 = 0.f, bm1 = 0.f;
        if (bias_m) {
            if (bmode == 1) { bm0 = bias_m[qkv_map_m(r)]; bm1 = bias_m[qkv_map_m(r + 8)]; }
            else            { bm0 = bias_m[r]; bm1 = bias_m[r + 8]; }
        }
        float zs0 = 0.f, zs1 = 0.f;
        #pragma unroll
        for (int nt = 0; nt < 4; nt++) {
            float* c = acc[mt][nt];
            int n = n0 + wn + 8 * nt + qid * 2;
            long long o0 = cbase + (long long)r * Csm + n;
            long long o1 = cbase + (long long)(r + 8) * Csm + n;
            if (emode) {
                float e00 = __expf(c[0] * alpha - 2.0f);
                float e01 = __expf(c[1] * alpha - 2.0f);
                float e10 = __expf(c[2] * alpha - 2.0f);
                float e11 = __expf(c[3] * alpha - 2.0f);
                zs0 += e00 + e01; zs1 += e10 + e11;
                *(__half2*)((__half*)Cv + o0) = __floats2half2_rn(e00, e01);
                *(__half2*)((__half*)Cv + o1) = __floats2half2_rn(e10, e11);
                continue;
            }
            float bn0 = 0.f, bn1 = 0.f;
            if (bias_n) {
                if (bmode == 2) { bn0 = bias_n[qkv_map_v(n)]; bn1 = bias_n[qkv_map_v(n + 1)]; }
                else            { bn0 = bias_n[n]; bn1 = bias_n[n + 1]; }
            }
            float v00 = c[0] * alpha + bm0 + bn0;
            float v01 = c[1] * alpha + bm0 + bn1;
            float v10 = c[2] * alpha + bm1 + bn0;
            float v11 = c[3] * alpha + bm1 + bn1;
            if (rowscale) {
                float rs0 = 1.0f / rowscale[rsbase + n];
                float rs1 = 1.0f / rowscale[rsbase + n + 1];
                v00 *= rs0; v01 *= rs1; v10 *= rs0; v11 *= rs1;
            }
            if (c16) {
                *(__half2*)((__half*)Cv + o0) = __floats2half2_rn(v00, v01);
                *(__half2*)((__half*)Cv + o1) = __floats2half2_rn(v10, v11);
            } else {
                float* C = (float*)Cv;
                if (resid) {
                    v00 += resid[o0]; v01 += resid[o0 + 1];
                    v10 += resid[o1]; v11 += resid[o1 + 1];
                }
                *(float2*)(C + o0) = make_float2(v00, v01);
                *(float2*)(C + o1) = make_float2(v10, v11);
            }
        }
        if (emode) {
            zs0 += __shfl_xor_sync(0xffffffffu, zs0, 1);
            zs0 += __shfl_xor_sync(0xffffffffu, zs0, 2);
            zs1 += __shfl_xor_sync(0xffffffffu, zs1, 1);
            zs1 += __shfl_xor_sync(0xffffffffu, zs1, 2);
            if (qid == 0) {
                atomicAdd(&zsum[zbase + r], zs0);
                atomicAdd(&zsum[zbase + r + 8], zs1);
            }
        }
    }
}

// merged projection + QK launch:
// [0,2048):    Q,K projection producers -> bump g_cnt2a[ft*8+b]
// [2048,3072): V projection (independent)
// [3072,3584): QK logits->E consumers, wait on 2 counters == 8
__global__ void __launch_bounds__(256, 2)
hgemm_proj_qk(const float* __restrict__ b_qkv) {
    extern __shared__ char smem[];
    int bx = blockIdx.x;
    int tid = threadIdx.x;
    float* Zp;
    asm("cvta.global.u64 %0, %1;" : "=l"(Zp) : "l"(g_Z));
    if (bx < 2048) {
        int ft = bx & 31;            // feature tile 0..31
        int btile = bx >> 5;         // bt tile 0..63
        gemm_body(smem, g_wqkT, g_h, g_qkT, NC,
                  512, 512, BT, 0,
                  ft * 128, btile * 128,
                  1.0f, b_qkv, nullptr, nullptr, 1, 1, nullptr, 0, nullptr, 0, 0);
        __threadfence();
        __syncthreads();
        if (tid == 0) atomicAdd(&g_cnt2a[ft * 8 + (btile >> 3)], 1);
    } else if (bx < 3072) {
        int j = bx - 2048;
        gemm_body(smem, g_h, g_wqkT + 4096LL * 512, g_v2, NC,
                  512, 512, NF, 0,
                  (j >> 4) * 128, (j & 15) * 128,
                  1.0f, nullptr, b_qkv, nullptr, 1, 2, nullptr, 0, nullptr, 0, 0);
    } else {
        int j = bx - 3072;           // 0..511
        int z = j >> 4;
        int zi = z & 3, zo = z >> 2;
        int mt4 = (j >> 2) & 3, nt4 = j & 3;
        int ftA = zi * 4 + mt4;
        int ftB = 16 + zi * 4 + nt4;
        if (tid == 0) {
            while (atomicAdd(&g_cnt2a[ftA * 8 + zo], 0) < 8) { }
            while (atomicAdd(&g_cnt2a[ftB * 8 + zo], 0) < 8) { }
        }
        __syncthreads();
        gemm_body(smem,
                  g_qkT + (long long)zi * 512 * BT + (long long)zo * NT,
                  g_qkT + 2048LL * BT + (long long)zi * 512 * BT + (long long)zo * NT,
                  g_attnh, NT,
                  BT, BT, NC,
                  (long long)z * NC * NC, mt4 * 128, nt4 * 128,
                  1.0f / 32.0f, nullptr, nullptr, nullptr, 1, 0,
                  nullptr, 0, Zp, (long long)z * 512, 1);
    }
}

// merged AV + Out with tile-granular dependency counters.
__global__ void __launch_bounds__(256, 2)
hgemm_av_out(const float* __restrict__ b_out, const float* __restrict__ x,
             float* __restrict__ out) {
    extern __shared__ char smem[];
    int bx = blockIdx.x;
    int tid = threadIdx.x;
    float* Zp;
    asm("cvta.global.u64 %0, %1;" : "=l"(Zp) : "l"(g_Z));
    if (bx < 1024) {
        int z = bx >> 5;
        int zi = z & 3, zo = z >> 2;
        int tt = (bx >> 2) & 7, cc = bx & 3;
        gemm_body(smem,
                  g_v2 + zi * 512 + (long long)zo * NT * NF,
                  g_attnh + (long long)z * NC * NC,
                  g_av2, NC,
                  NF, NC, NF,
                  (long long)zi * 512 + (long long)zo * NT * NF,
                  tt * 128, cc * 128,
                  1.0f, nullptr, nullptr, nullptr, 1, 0,
                  Zp, (long long)z * 512, nullptr, 0, 0);
        __threadfence();
        __syncthreads();
        if (tid == 0) atomicAdd(&g_cnt[zo * 8 + tt], 1);
    } else {
        int j = bx - 1024;
        int b = j >> 5, tt = (j >> 2) & 7, cc = j & 3;
        if (tid == 0) {
            while (atomicAdd(&g_cnt[b * 8 + tt], 0) < 16) { }
        }
        __syncthreads();
        gemm_body(smem, g_av2 + (long long)b * NT * NF, g_woutT, out, NF,
                  NF, NF, NC, (long long)b * NT * NC,
                  tt * 128, cc * 128,
                  1.0f, nullptr, b_out, x, 0, 0, nullptr, 0, nullptr, 0, 0);
    }
}

extern "C" void kernel_launch(void* const* d_in, const int* in_sizes, int n_in,
                              void* d_out, int out_size) {
    const float* x        = (const float*)d_in[0];
    const float* gn_scale = (const float*)d_in[1];
    const float* gn_bias  = (const float*)d_in[2];
    const float* w_qkv    = (const float*)d_in[3];
    const float* b_qkv    = (const float*)d_in[4];
    const float* w_out    = (const float*)d_in[5];
    const float* b_out    = (const float*)d_in[6];
    float* out = (float*)d_out;

    cudaFuncSetAttribute(hgemm_proj_qk, cudaFuncAttributeMaxDynamicSharedMemorySize, GSMEM);
    cudaFuncSetAttribute(hgemm_av_out,  cudaFuncAttributeMaxDynamicSharedMemorySize, GSMEM);

    // 0: merged prep (groupnorm + transposes + counter/Z zero)
    gn_tr<<<1472, 256>>>(x, gn_scale, gn_bias, w_qkv, w_out);

    // 1: Q,K projection + V projection + QK logits->E, counter-chained
    hgemm_proj_qk<<<3584, 256, GSMEM>>>(b_qkv);

    // 2: AV + Out merged with dependency counters
    hgemm_av_out<<<1280, 256, GSMEM>>>(b_out, x, out);
}